// round 8
// baseline (speedup 1.0000x reference)
#include <cuda_runtime.h>
#include <cuda_fp16.h>
#include <mma.h>
#include <math.h>

using namespace nvcuda;

#define N_NODES 50000
#define N_EDGES 1600000
#define E_TOT   (N_EDGES + N_NODES)
#define HID     128
#define IND     13
#define OUTD    5
#define SCAN_BS 512
#define NBLK    ((N_NODES + SCAN_BS - 1) / SCAN_BS)   // 98

// ---------------- scratch (static device globals; no allocation) ----------------
__device__ int    g_ssrc[E_TOT];           // CSR-sorted source indices (by dst)
__device__ int    g_cnt[N_NODES];
__device__ int    g_off[N_NODES + 1];
__device__ int    g_cur[N_NODES];
__device__ int    g_bsum[NBLK + 1];
__device__ __align__(16) __half g_hh[N_NODES * HID];    // transformed features, fp16
__device__ __align__(16) __half g_feath[N_NODES * HID]; // layer input, fp16 (for WMMA)
__device__ __align__(16) __half g_W2h[HID * HID];       // W2 in fp16
__device__ float4 g_feat[N_NODES * 32];    // layer input/output [N][128] as float4
__device__ float  g_as[N_NODES];
__device__ float  g_ad[N_NODES];
__device__ float  g_h5[N_NODES * OUTD];

// ---------------- CSR build ----------------
__global__ void k_zero_cnt() {
    int i = blockIdx.x * blockDim.x + threadIdx.x;
    if (i < N_NODES) g_cnt[i] = 0;
}

__global__ void k_hist(const int* __restrict__ ei) {
    int e = blockIdx.x * blockDim.x + threadIdx.x;
    if (e >= E_TOT) return;
    int d = (e < N_EDGES) ? ei[N_EDGES + e] : e - N_EDGES;   // int32 (JAX x64 disabled)
    atomicAdd(&g_cnt[d], 1);
}

__global__ void k_blocksum() {
    __shared__ int sm[SCAN_BS];
    int i = blockIdx.x * SCAN_BS + threadIdx.x;
    sm[threadIdx.x] = (i < N_NODES) ? g_cnt[i] : 0;
    __syncthreads();
    for (int o = SCAN_BS / 2; o > 0; o >>= 1) {
        if (threadIdx.x < o) sm[threadIdx.x] += sm[threadIdx.x + o];
        __syncthreads();
    }
    if (threadIdx.x == 0) g_bsum[blockIdx.x] = sm[0];
}

__global__ void k_scantop() {          // parallel scan over NBLK(=98) block sums
    __shared__ int sm[128];
    int t = threadIdx.x;
    int v = (t < NBLK) ? g_bsum[t] : 0;
    sm[t] = v;
    __syncthreads();
    for (int o = 1; o < 128; o <<= 1) {
        int u = (t >= o) ? sm[t - o] : 0;
        __syncthreads();
        sm[t] += u;
        __syncthreads();
    }
    if (t < NBLK) g_bsum[t] = sm[t] - v;      // exclusive
    if (t == 127) g_off[N_NODES] = sm[127];   // == E_TOT
}

__global__ void k_offsets() {
    __shared__ int sm[SCAN_BS];
    int i = blockIdx.x * SCAN_BS + threadIdx.x;
    int v = (i < N_NODES) ? g_cnt[i] : 0;
    sm[threadIdx.x] = v;
    __syncthreads();
    for (int o = 1; o < SCAN_BS; o <<= 1) {          // Hillis-Steele inclusive
        int t = (threadIdx.x >= o) ? sm[threadIdx.x - o] : 0;
        __syncthreads();
        sm[threadIdx.x] += t;
        __syncthreads();
    }
    if (i < N_NODES) {
        int excl = sm[threadIdx.x] - v + g_bsum[blockIdx.x];
        g_off[i] = excl;
        g_cur[i] = excl;
    }
}

__global__ void k_fill(const int* __restrict__ ei) {
    int e = blockIdx.x * blockDim.x + threadIdx.x;
    if (e >= E_TOT) return;
    int s, d;
    if (e < N_EDGES) { s = ei[e]; d = ei[N_EDGES + e]; }
    else             { s = d = e - N_EDGES; }
    int pos = atomicAdd(&g_cur[d], 1);
    g_ssrc[pos] = s;
}

// ---------------- helpers ----------------
__device__ __forceinline__ uint2 pack_half4(float a, float b, float c, float d) {
    __half2 h0 = __float22half2_rn(make_float2(a, b));
    __half2 h1 = __float22half2_rn(make_float2(c, d));
    uint2 u;
    u.x = *reinterpret_cast<unsigned*>(&h0);
    u.y = *reinterpret_cast<unsigned*>(&h1);
    return u;
}
__device__ __forceinline__ float4 unpack_half4(uint2 u) {
    __half2 h0 = *reinterpret_cast<__half2*>(&u.x);
    __half2 h1 = *reinterpret_cast<__half2*>(&u.y);
    float2 f0 = __half22float2(h0), f1 = __half22float2(h1);
    return make_float4(f0.x, f0.y, f1.x, f1.y);
}

// ---------------- layer 1 GEMM (K=13) + fused attention dots ----------------
__global__ void k_gemm1(const float* __restrict__ x, const float* __restrict__ W1,
                        const float* __restrict__ a_src, const float* __restrict__ a_dst) {
    __shared__ __align__(16) float Ws[IND * HID];
    __shared__ __align__(16) float As[HID];
    __shared__ __align__(16) float Ad[HID];
    for (int i = threadIdx.x; i < IND * HID; i += blockDim.x) Ws[i] = W1[i];
    for (int i = threadIdx.x; i < HID; i += blockDim.x) { As[i] = a_src[i]; Ad[i] = a_dst[i]; }
    __syncthreads();
    int warp = threadIdx.x >> 5, lane = threadIdx.x & 31;
    int node = blockIdx.x * 8 + warp;
    if (node >= N_NODES) return;
    float xv[IND];
#pragma unroll
    for (int k = 0; k < IND; ++k) xv[k] = x[node * IND + k];
    float4 acc = {0.f, 0.f, 0.f, 0.f};
#pragma unroll
    for (int k = 0; k < IND; ++k) {
        float4 w = *(const float4*)&Ws[k * HID + lane * 4];
        acc.x += xv[k] * w.x; acc.y += xv[k] * w.y;
        acc.z += xv[k] * w.z; acc.w += xv[k] * w.w;
    }
    ((uint2*)g_hh)[node * 32 + lane] = pack_half4(acc.x, acc.y, acc.z, acc.w);
    float4 a1 = *(const float4*)&As[lane * 4];
    float4 a2 = *(const float4*)&Ad[lane * 4];
    float s1 = acc.x * a1.x + acc.y * a1.y + acc.z * a1.z + acc.w * a1.w;
    float s2 = acc.x * a2.x + acc.y * a2.y + acc.z * a2.z + acc.w * a2.w;
#pragma unroll
    for (int o = 16; o; o >>= 1) {
        s1 += __shfl_xor_sync(0xffffffffu, s1, o);
        s2 += __shfl_xor_sync(0xffffffffu, s2, o);
    }
    if (lane == 0) { g_as[node] = s1; g_ad[node] = s2; }
}

// ---------------- W2 -> fp16 ----------------
__global__ void k_cvtW2(const float* __restrict__ W) {
    int i = blockIdx.x * blockDim.x + threadIdx.x;
    if (i < HID * HID) g_W2h[i] = __float2half(W[i]);
}

// ---------------- layer 2 GEMM via WMMA: 64 rows x 128 cols per block ----------
// block 256 (8 warps). Warp w: row-tile w>>1 (16 rows), col-tiles (w&1)*4..+3.
#define FS_LD 136
__global__ void k_gemm2_wmma() {
    __shared__ __align__(16) __half Fs[64 * FS_LD];
    __shared__ __align__(16) float  Os[8 * 256];       // per-warp 16x16 staging
    int rowBase = blockIdx.x * 64;
    int warp = threadIdx.x >> 5, lane = threadIdx.x & 31;
    // load feat tile 64x128 fp16 (uint4 = 8 halves)
    for (int v = threadIdx.x * 8; v < 64 * HID; v += 256 * 8) {
        int r = v >> 7, c = v & 127;
        int gr = rowBase + r;
        uint4 d = (gr < N_NODES) ? *(const uint4*)&g_feath[gr * HID + c]
                                 : make_uint4(0u, 0u, 0u, 0u);
        *(uint4*)&Fs[r * FS_LD + c] = d;
    }
    __syncthreads();
    int rowTile = warp >> 1;
    int colTile0 = (warp & 1) * 4;
    wmma::fragment<wmma::accumulator, 16, 16, 16, float> acc[4];
#pragma unroll
    for (int t = 0; t < 4; ++t) wmma::fill_fragment(acc[t], 0.f);
    for (int k = 0; k < HID; k += 16) {
        wmma::fragment<wmma::matrix_a, 16, 16, 16, __half, wmma::row_major> a;
        wmma::load_matrix_sync(a, &Fs[rowTile * 16 * FS_LD + k], FS_LD);
#pragma unroll
        for (int t = 0; t < 4; ++t) {
            wmma::fragment<wmma::matrix_b, 16, 16, 16, __half, wmma::row_major> b;
            wmma::load_matrix_sync(b, &g_W2h[k * HID + (colTile0 + t) * 16], HID);
            wmma::mma_sync(acc[t], a, b, acc[t]);
        }
    }
    // epilogue: stage fp32 tile in smem, pack to fp16 g_hh
    float* os = &Os[warp * 256];
#pragma unroll
    for (int t = 0; t < 4; ++t) {
        wmma::store_matrix_sync(os, acc[t], 16, wmma::mem_row_major);
        __syncwarp();
        int r = lane >> 1, c8 = (lane & 1) * 8;
        int gr = rowBase + rowTile * 16 + r;
        if (gr < N_NODES) {
            int gc = (colTile0 + t) * 16 + c8;
            const float* p = &os[r * 16 + c8];
            __half2* dst = (__half2*)&g_hh[gr * HID + gc];
#pragma unroll
            for (int q = 0; q < 4; ++q)
                dst[q] = __float22half2_rn(make_float2(p[2 * q], p[2 * q + 1]));
        }
        __syncwarp();
    }
}

// attention dots for layer 2 (h row . a_src / a_dst), h in fp16
__global__ void k_rowdot(const float* __restrict__ a_src, const float* __restrict__ a_dst) {
    int warp = threadIdx.x >> 5, lane = threadIdx.x & 31;
    int node = blockIdx.x * 8 + warp;
    if (node >= N_NODES) return;
    float4 hv = unpack_half4(((const uint2*)g_hh)[node * 32 + lane]);
    float4 a1 = make_float4(a_src[lane * 4], a_src[lane * 4 + 1], a_src[lane * 4 + 2], a_src[lane * 4 + 3]);
    float4 a2 = make_float4(a_dst[lane * 4], a_dst[lane * 4 + 1], a_dst[lane * 4 + 2], a_dst[lane * 4 + 3]);
    float s1 = hv.x * a1.x + hv.y * a1.y + hv.z * a1.z + hv.w * a1.w;
    float s2 = hv.x * a2.x + hv.y * a2.y + hv.z * a2.z + hv.w * a2.w;
#pragma unroll
    for (int o = 16; o; o >>= 1) {
        s1 += __shfl_xor_sync(0xffffffffu, s1, o);
        s2 += __shfl_xor_sync(0xffffffffu, s2, o);
    }
    if (lane == 0) { g_as[node] = s1; g_ad[node] = s2; }
}

// ---------------- fused softmax-aggregation, F=128 (warp per node, fp16 gather) ----
__device__ __forceinline__ float leaky(float e) { return e > 0.f ? e : 0.2f * e; }

__global__ void k_agg128(const float* __restrict__ b, int relu) {
    int warp = threadIdx.x >> 5, lane = threadIdx.x & 31;
    int i = blockIdx.x * 8 + warp;
    if (i >= N_NODES) return;
    int start = g_off[i], end = g_off[i + 1];
    float adi = g_ad[i];
    // pass 1: per-target max (lanes parallel over edges)
    float m = -1e30f;
    for (int j = start + lane; j < end; j += 32)
        m = fmaxf(m, leaky(g_as[g_ssrc[j]] + adi));
#pragma unroll
    for (int o = 16; o; o >>= 1) m = fmaxf(m, __shfl_xor_sync(0xffffffffu, m, o));
    // pass 2: warp-cooperative weighted gather, 4x unrolled for MLP
    float4 acc = {0.f, 0.f, 0.f, 0.f};
    float denom = 0.f;
    const uint2* hh = (const uint2*)g_hh;
    int j = start;
    for (; j + 4 <= end; j += 4) {
        int s0 = g_ssrc[j], s1 = g_ssrc[j + 1], s2 = g_ssrc[j + 2], s3 = g_ssrc[j + 3];
        float e0 = g_as[s0] + adi, e1 = g_as[s1] + adi,
              e2 = g_as[s2] + adi, e3 = g_as[s3] + adi;
        uint2 p0 = hh[s0 * 32 + lane], p1 = hh[s1 * 32 + lane],
              p2 = hh[s2 * 32 + lane], p3 = hh[s3 * 32 + lane];
        float x0 = __expf(leaky(e0) - m), x1 = __expf(leaky(e1) - m),
              x2 = __expf(leaky(e2) - m), x3 = __expf(leaky(e3) - m);
        denom += (x0 + x1) + (x2 + x3);
        float4 h0 = unpack_half4(p0), h1 = unpack_half4(p1),
               h2 = unpack_half4(p2), h3 = unpack_half4(p3);
        acc.x += x0 * h0.x + x1 * h1.x + x2 * h2.x + x3 * h3.x;
        acc.y += x0 * h0.y + x1 * h1.y + x2 * h2.y + x3 * h3.y;
        acc.z += x0 * h0.z + x1 * h1.z + x2 * h2.z + x3 * h3.z;
        acc.w += x0 * h0.w + x1 * h1.w + x2 * h2.w + x3 * h3.w;
    }
    for (; j < end; ++j) {
        int s = g_ssrc[j];
        float ex = __expf(leaky(g_as[s] + adi) - m);
        denom += ex;
        float4 hv = unpack_half4(hh[s * 32 + lane]);
        acc.x += ex * hv.x; acc.y += ex * hv.y;
        acc.z += ex * hv.z; acc.w += ex * hv.w;
    }
    float inv = 1.f / (denom + 1e-16f);
    float4 bv = make_float4(b[lane * 4], b[lane * 4 + 1], b[lane * 4 + 2], b[lane * 4 + 3]);
    float4 r;
    r.x = acc.x * inv + bv.x; r.y = acc.y * inv + bv.y;
    r.z = acc.z * inv + bv.z; r.w = acc.w * inv + bv.w;
    if (relu) {
        r.x = fmaxf(r.x, 0.f); r.y = fmaxf(r.y, 0.f);
        r.z = fmaxf(r.z, 0.f); r.w = fmaxf(r.w, 0.f);
    }
    g_feat[i * 32 + lane] = r;                                // fp32 (for gemm3)
    ((uint2*)g_feath)[i * 32 + lane] = pack_half4(r.x, r.y, r.z, r.w);  // fp16 (for WMMA gemm2)
}

// ---------------- layer 3 GEMM (K=128 -> 5) + fused attention dots ----------------
__global__ void k_gemm3(const float* __restrict__ W3,
                        const float* __restrict__ a_src, const float* __restrict__ a_dst) {
    __shared__ float Ws[HID * OUTD];
    __shared__ float As[OUTD], Ad[OUTD];
    for (int i = threadIdx.x; i < HID * OUTD; i += blockDim.x) Ws[i] = W3[i];
    if (threadIdx.x < OUTD) { As[threadIdx.x] = a_src[threadIdx.x]; Ad[threadIdx.x] = a_dst[threadIdx.x]; }
    __syncthreads();
    int warp = threadIdx.x >> 5, lane = threadIdx.x & 31;
    int node = blockIdx.x * 8 + warp;
    if (node >= N_NODES) return;
    float4 f = g_feat[node * 32 + lane];
    int k0 = lane * 4;
    float hc[OUTD];
#pragma unroll
    for (int c = 0; c < OUTD; ++c) {
        float s = f.x * Ws[(k0 + 0) * OUTD + c] + f.y * Ws[(k0 + 1) * OUTD + c]
                + f.z * Ws[(k0 + 2) * OUTD + c] + f.w * Ws[(k0 + 3) * OUTD + c];
#pragma unroll
        for (int o = 16; o; o >>= 1) s += __shfl_xor_sync(0xffffffffu, s, o);
        hc[c] = s;
    }
    if (lane == 0) {
        float s1 = 0.f, s2 = 0.f;
#pragma unroll
        for (int c = 0; c < OUTD; ++c) {
            g_h5[node * OUTD + c] = hc[c];
            s1 += hc[c] * As[c];
            s2 += hc[c] * Ad[c];
        }
        g_as[node] = s1; g_ad[node] = s2;
    }
}

// ---------------- fused aggregation F=5 + bias + log_softmax (warp per node) -------
__global__ void k_agg5(const float* __restrict__ b3, float* __restrict__ out) {
    int warp = threadIdx.x >> 5, lane = threadIdx.x & 31;
    int i = blockIdx.x * 8 + warp;
    if (i >= N_NODES) return;
    int start = g_off[i], end = g_off[i + 1];
    float adi = g_ad[i];
    float m = -1e30f;
    for (int j = start + lane; j < end; j += 32)
        m = fmaxf(m, leaky(g_as[g_ssrc[j]] + adi));
#pragma unroll
    for (int o = 16; o; o >>= 1) m = fmaxf(m, __shfl_xor_sync(0xffffffffu, m, o));
    float a0 = 0.f, a1 = 0.f, a2 = 0.f, a3 = 0.f, a4 = 0.f, denom = 0.f;
    for (int j = start + lane; j < end; j += 32) {
        int s = g_ssrc[j];
        float ex = __expf(leaky(g_as[s] + adi) - m);
        denom += ex;
        const float* hp = &g_h5[s * OUTD];
        a0 += ex * hp[0]; a1 += ex * hp[1]; a2 += ex * hp[2];
        a3 += ex * hp[3]; a4 += ex * hp[4];
    }
#pragma unroll
    for (int o = 16; o; o >>= 1) {
        denom += __shfl_xor_sync(0xffffffffu, denom, o);
        a0 += __shfl_xor_sync(0xffffffffu, a0, o);
        a1 += __shfl_xor_sync(0xffffffffu, a1, o);
        a2 += __shfl_xor_sync(0xffffffffu, a2, o);
        a3 += __shfl_xor_sync(0xffffffffu, a3, o);
        a4 += __shfl_xor_sync(0xffffffffu, a4, o);
    }
    if (lane == 0) {
        float inv = 1.f / (denom + 1e-16f);
        float v[OUTD] = {a0 * inv + b3[0], a1 * inv + b3[1], a2 * inv + b3[2],
                         a3 * inv + b3[3], a4 * inv + b3[4]};
        float mx = -1e30f;
#pragma unroll
        for (int c = 0; c < OUTD; ++c) mx = fmaxf(mx, v[c]);
        float se = 0.f;
#pragma unroll
        for (int c = 0; c < OUTD; ++c) se += __expf(v[c] - mx);
        float lse = mx + logf(se);
#pragma unroll
        for (int c = 0; c < OUTD; ++c) out[i * OUTD + c] = v[c] - lse;
    }
}

// ---------------- launch ----------------
extern "C" void kernel_launch(void* const* d_in, const int* in_sizes, int n_in,
                              void* d_out, int out_size) {
    const float* x   = (const float*)d_in[0];
    const int*   ei  = (const int*)d_in[1];       // int32: JAX x64 is disabled
    const float* W1  = (const float*)d_in[2];
    const float* as1 = (const float*)d_in[3];
    const float* ad1 = (const float*)d_in[4];
    const float* b1  = (const float*)d_in[5];
    const float* W2  = (const float*)d_in[6];
    const float* as2 = (const float*)d_in[7];
    const float* ad2 = (const float*)d_in[8];
    const float* b2  = (const float*)d_in[9];
    const float* W3  = (const float*)d_in[10];
    const float* as3 = (const float*)d_in[11];
    const float* ad3 = (const float*)d_in[12];
    const float* b3  = (const float*)d_in[13];
    float* out = (float*)d_out;

    // CSR build (shared by all 3 layers; rebuilt every call — no caching)
    k_zero_cnt<<<(N_NODES + 255) / 256, 256>>>();
    k_hist<<<(E_TOT + 255) / 256, 256>>>(ei);
    k_blocksum<<<NBLK, SCAN_BS>>>();
    k_scantop<<<1, 128>>>();
    k_offsets<<<NBLK, SCAN_BS>>>();
    k_fill<<<(E_TOT + 255) / 256, 256>>>(ei);

    int nwb = (N_NODES + 7) / 8;   // warp-per-node grids

    // layer 1 (+ W2 conversion, independent)
    k_cvtW2<<<(HID * HID + 255) / 256, 256>>>(W2);
    k_gemm1<<<nwb, 256>>>(x, W1, as1, ad1);
    k_agg128<<<nwb, 256>>>(b1, 1);
    // layer 2
    k_gemm2_wmma<<<(N_NODES + 63) / 64, 256>>>();
    k_rowdot<<<nwb, 256>>>(as2, ad2);
    k_agg128<<<nwb, 256>>>(b2, 1);
    // layer 3
    k_gemm3<<<nwb, 256>>>(W3, as3, ad3);
    k_agg5<<<nwb, 256>>>(b3, out);
}